// round 7
// baseline (speedup 1.0000x reference)
#include <cuda_runtime.h>
#include <cuda_bf16.h>
#include <cstdint>

#define BB 4
#define HH 16
#define SSEQ 2048
#define DDIM 128
#define BM 128
#define BN 64
#define NTILES (SSEQ / BN)
#define NTH 256

__device__ float g_inv_rowsum[BB * HH * SSEQ];

// smem word layout (uint32 words, each = 2 bf16). Row stride 136 bf16 = 272 B.
#define QST 136
#define QROWW 68
#define Q_HI_W 0
#define Q_LO_W (128 * QROWW)
#define KBUF_HI_W(buf) (17408 + (buf) * 8704)
#define KBUF_LO_W(buf) (KBUF_HI_W(buf) + 4352)
#define VBUF_HI_W(buf) (34816 + (buf) * 8704)
#define VBUF_LO_W(buf) (VBUF_HI_W(buf) + 4352)
#define SMEM_WORDS 52224
#define SMEM_BYTES (SMEM_WORDS * 4)    // 208,896 B

__device__ __forceinline__ uint32_t smem_u32(const void* p) {
    uint32_t a;
    asm("{ .reg .u64 t; cvta.to.shared.u64 t, %1; cvt.u32.u64 %0, t; }" : "=r"(a) : "l"(p));
    return a;
}

__device__ __forceinline__ void mma_bf16(float c[4],
                                         uint32_t a0, uint32_t a1, uint32_t a2, uint32_t a3,
                                         uint32_t b0, uint32_t b1)
{
    asm volatile(
        "mma.sync.aligned.m16n8k16.row.col.f32.bf16.bf16.f32 "
        "{%0,%1,%2,%3}, {%4,%5,%6,%7}, {%8,%9}, {%0,%1,%2,%3};"
        : "+f"(c[0]), "+f"(c[1]), "+f"(c[2]), "+f"(c[3])
        : "r"(a0), "r"(a1), "r"(a2), "r"(a3), "r"(b0), "r"(b1));
}

__device__ __forceinline__ void ldsm4(uint32_t& r0, uint32_t& r1, uint32_t& r2, uint32_t& r3,
                                      uint32_t saddr)
{
    asm volatile("ldmatrix.sync.aligned.m8n8.x4.shared.b16 {%0,%1,%2,%3}, [%4];"
                 : "=r"(r0), "=r"(r1), "=r"(r2), "=r"(r3) : "r"(saddr));
}
__device__ __forceinline__ void ldsm4t(uint32_t& r0, uint32_t& r1, uint32_t& r2, uint32_t& r3,
                                       uint32_t saddr)
{
    asm volatile("ldmatrix.sync.aligned.m8n8.x4.trans.shared.b16 {%0,%1,%2,%3}, [%4];"
                 : "=r"(r0), "=r"(r1), "=r"(r2), "=r"(r3) : "r"(saddr));
}

__device__ __forceinline__ uint32_t prmt7632(uint32_t a, uint32_t b)
{
    uint32_t d;
    asm("prmt.b32 %0, %1, %2, 0x7632;" : "=r"(d) : "r"(a), "r"(b));
    return d;
}

// truncation-based fp32 pair -> bf16 hi/lo split (x0 in low half). ~6 instr.
// hi = trunc(x) (err <= 2^-8 rel); lo = x - hi is exact in fp32, then trunc (err <= 2^-16 rel)
__device__ __forceinline__ void split2t(float x0, float x1, uint32_t& hi, uint32_t& lo)
{
    uint32_t i0 = __float_as_uint(x0), i1 = __float_as_uint(x1);
    hi = prmt7632(i0, i1);
    float l0 = x0 - __uint_as_float(i0 & 0xFFFF0000u);
    float l1 = x1 - __uint_as_float(i1 & 0xFFFF0000u);
    lo = prmt7632(__float_as_uint(l0), __float_as_uint(l1));
}

// register-resident staging: 8 float4 per thread = one 64x128 fp32 tile per CTA
__device__ __forceinline__ void load8(const float4* p4, int tid, float4 r[8])
{
    #pragma unroll
    for (int it = 0; it < 8; it++) r[it] = p4[it * NTH + tid];
}
// one staging iteration: convert + store a single float4 (interleaved into MMA loops)
__device__ __forceinline__ void stage_iter(const float4 x, uint32_t* hi, uint32_t* lo,
                                           int tid, int it)
{
    int idx = it * NTH + tid;
    int row = idx >> 5;
    int c4  = (idx & 31) << 2;
    int w   = (row * QST + c4) >> 1;
    uint32_t h0, l0, h1, l1;
    split2t(x.x, x.y, h0, l0);
    split2t(x.z, x.w, h1, l1);
    *(uint2*)(hi + w) = make_uint2(h0, h1);
    *(uint2*)(lo + w) = make_uint2(l0, l1);
}

__global__ __launch_bounds__(NTH, 1)
void attn_mma(const float* __restrict__ q,
              const float* __restrict__ k,
              const float* __restrict__ v,
              const int*   __restrict__ mask,
              float* __restrict__ out,
              float* __restrict__ attn)
{
    extern __shared__ uint32_t SW[];
    const uint32_t sb = smem_u32(SW);

    const int tid  = threadIdx.x;
    const int lane = tid & 31;
    const int w16  = (tid >> 5) * 16;
    const int g    = lane >> 2;
    const int tg   = lane & 3;

    const int h      = blockIdx.x;
    const int qblock = blockIdx.y;
    const int b      = blockIdx.z;
    const int bh     = b * HH + h;
    const int q0     = qblock * BM;
    const size_t head = (size_t)bh * SSEQ * DDIM;

    // ---- stage Q tile (128x128) bf16 hi/lo ----
    {
        const float4* qp4 = (const float4*)(q + head + (size_t)q0 * DDIM);
        #pragma unroll
        for (int it = 0; it < 16; it++) {
            int idx = it * NTH + tid;
            int row = idx >> 5;
            int c4  = (idx & 31) << 2;
            float4 x = qp4[idx];
            uint32_t h0, l0, h1, l1;
            split2t(x.x, x.y, h0, l0);
            split2t(x.z, x.w, h1, l1);
            int w = (row * QST + c4) >> 1;
            *(uint2*)(SW + Q_HI_W + w) = make_uint2(h0, h1);
            *(uint2*)(SW + Q_LO_W + w) = make_uint2(l0, l1);
        }
    }
    // stage K/V tile 0 into buffer 0
    {
        float4 r[8];
        load8((const float4*)(k + head), tid, r);
        #pragma unroll
        for (int it = 0; it < 8; it++)
            stage_iter(r[it], SW + KBUF_HI_W(0), SW + KBUF_LO_W(0), tid, it);
        load8((const float4*)(v + head), tid, r);
        #pragma unroll
        for (int it = 0; it < 8; it++)
            stage_iter(r[it], SW + VBUF_HI_W(0), SW + VBUF_LO_W(0), tid, it);
    }

    // ldmatrix lane-address bases (byte offsets within a tile)
    const uint32_t a_byte  = (uint32_t)(((w16 + (lane & 15)) * QST + ((lane & 16) ? 8 : 0)) * 2);
    const uint32_t qhi_ad  = sb + Q_HI_W * 4 + a_byte;
    const uint32_t qlo_ad  = sb + Q_LO_W * 4 + a_byte;
    const uint32_t bk_byte = (uint32_t)((((lane & 7) + ((lane & 16) ? 8 : 0)) * QST +
                                         ((lane & 8) ? 8 : 0)) * 2);
    const uint32_t bv_byte = (uint32_t)((((lane & 7) + ((lane & 8) ? 8 : 0)) * QST) * 2 +
                                        ((lane & 16) ? 16 : 0));

    // accumulators
    float o[16][4];
    #pragma unroll
    for (int jn = 0; jn < 16; jn++)
        #pragma unroll
        for (int p = 0; p < 4; p++) o[jn][p] = 0.f;
    float rsum0 = 0.f, rsum1 = 0.f;

    const float scale = 0.08838834764831843f;   // 1/sqrt(128)
    const int r0 = q0 + w16 + g;
    const int* m0p = mask + ((size_t)b * SSEQ + r0) * SSEQ;
    const int* m1p = m0p + (size_t)8 * SSEQ;
    float* a0p = attn + ((size_t)bh * SSEQ + r0) * SSEQ;
    float* a1p = a0p + (size_t)8 * SSEQ;

    __syncthreads();

    for (int kb = 0; kb < NTILES; kb++) {
        const int buf = kb & 1;
        const int k0  = kb * BN;
        const bool pf = (kb + 1 < NTILES);
        const size_t nk0 = (size_t)(k0 + BN) * DDIM;

        // ---- issue next-tile K loads + this tile's mask loads (latency hidden by score MMAs) ----
        float4 streg[8];
        if (pf) load8((const float4*)(k + head + nk0), tid, streg);
        int2 mv0[8], mv1[8];
        #pragma unroll
        for (int j = 0; j < 8; j++) {
            const int c = k0 + tg * 2 + j * 8;
            mv0[j] = *(const int2*)(m0p + c);
            mv1[j] = *(const int2*)(m1p + c);
        }

        uint32_t* knhi = SW + KBUF_HI_W(buf ^ 1);
        uint32_t* knlo = SW + KBUF_LO_W(buf ^ 1);
        uint32_t* vnhi = SW + VBUF_HI_W(buf ^ 1);
        uint32_t* vnlo = SW + VBUF_LO_W(buf ^ 1);

        const uint32_t khi_ad = sb + KBUF_HI_W(buf) * 4 + bk_byte;
        const uint32_t klo_ad = sb + KBUF_LO_W(buf) * 4 + bk_byte;
        const uint32_t vhi_ad = sb + VBUF_HI_W(buf) * 4 + bv_byte;
        const uint32_t vlo_ad = sb + VBUF_LO_W(buf) * 4 + bv_byte;

        // ---- score GEMM: sc[16][64] = Q K^T, 3-way split; K(next) staging interleaved ----
        float sc[8][4];
        #pragma unroll
        for (int j = 0; j < 8; j++)
            #pragma unroll
            for (int p = 0; p < 4; p++) sc[j][p] = 0.f;

        #pragma unroll
        for (int ks = 0; ks < 8; ks++) {
            uint32_t ah0, ah1, ah2, ah3, al0, al1, al2, al3;
            ldsm4(ah0, ah1, ah2, ah3, qhi_ad + ks * 32);
            ldsm4(al0, al1, al2, al3, qlo_ad + ks * 32);
            #pragma unroll
            for (int jp = 0; jp < 4; jp++) {
                uint32_t b0, b1, b2, b3, c0, c1, c2, c3;
                ldsm4(b0, b1, b2, b3, khi_ad + ks * 32 + jp * (16 * QST * 2));
                ldsm4(c0, c1, c2, c3, klo_ad + ks * 32 + jp * (16 * QST * 2));
                mma_bf16(sc[2 * jp],     ah0, ah1, ah2, ah3, b0, b1);
                mma_bf16(sc[2 * jp],     ah0, ah1, ah2, ah3, c0, c1);
                mma_bf16(sc[2 * jp],     al0, al1, al2, al3, b0, b1);
                mma_bf16(sc[2 * jp + 1], ah0, ah1, ah2, ah3, b2, b3);
                mma_bf16(sc[2 * jp + 1], ah0, ah1, ah2, ah3, c2, c3);
                mma_bf16(sc[2 * jp + 1], al0, al1, al2, al3, b2, b3);
            }
            if (pf) stage_iter(streg[ks], knhi, knlo, tid, ks);   // interleaved K(next) staging
        }

        // ---- issue next-tile V loads (latency hidden by epilogue + PV MMAs) ----
        if (pf) load8((const float4*)(v + head + nk0), tid, streg);

        // ---- epilogue: mask + exp, write unnormalized attn, pack e hi/lo ----
        uint32_t eh[16], el[16];
        #pragma unroll
        for (int j = 0; j < 8; j++) {
            const int c = k0 + tg * 2 + j * 8;
            float e00 = mv0[j].x ? __expf(sc[j][0] * scale) : 0.f;
            float e01 = mv0[j].y ? __expf(sc[j][1] * scale) : 0.f;
            float e10 = mv1[j].x ? __expf(sc[j][2] * scale) : 0.f;
            float e11 = mv1[j].y ? __expf(sc[j][3] * scale) : 0.f;
            *(float2*)(a0p + c) = make_float2(e00, e01);
            *(float2*)(a1p + c) = make_float2(e10, e11);
            rsum0 += e00 + e01;
            rsum1 += e10 + e11;
            split2t(e00, e01, eh[j * 2], el[j * 2]);
            split2t(e10, e11, eh[j * 2 + 1], el[j * 2 + 1]);
        }

        // ---- PV GEMM: o[16][128] += e[16x64] * V[64x128], 3-way split; V(next) interleaved ----
        #pragma unroll
        for (int ks = 0; ks < 4; ks++) {
            uint32_t ah0 = eh[ks * 4 + 0], ah1 = eh[ks * 4 + 1];
            uint32_t ah2 = eh[ks * 4 + 2], ah3 = eh[ks * 4 + 3];
            uint32_t al0 = el[ks * 4 + 0], al1 = el[ks * 4 + 1];
            uint32_t al2 = el[ks * 4 + 2], al3 = el[ks * 4 + 3];
            #pragma unroll
            for (int jnp = 0; jnp < 8; jnp++) {
                uint32_t b0, b1, b2, b3, c0, c1, c2, c3;
                ldsm4t(b0, b1, b2, b3, vhi_ad + ks * (16 * QST * 2) + jnp * 32);
                ldsm4t(c0, c1, c2, c3, vlo_ad + ks * (16 * QST * 2) + jnp * 32);
                mma_bf16(o[2 * jnp],     ah0, ah1, ah2, ah3, b0, b1);
                mma_bf16(o[2 * jnp],     ah0, ah1, ah2, ah3, c0, c1);
                mma_bf16(o[2 * jnp],     al0, al1, al2, al3, b0, b1);
                mma_bf16(o[2 * jnp + 1], ah0, ah1, ah2, ah3, b2, b3);
                mma_bf16(o[2 * jnp + 1], ah0, ah1, ah2, ah3, c2, c3);
                mma_bf16(o[2 * jnp + 1], al0, al1, al2, al3, b2, b3);
            }
            if (pf) {                                            // interleaved V(next) staging
                stage_iter(streg[2 * ks],     vnhi, vnlo, tid, 2 * ks);
                stage_iter(streg[2 * ks + 1], vnhi, vnlo, tid, 2 * ks + 1);
            }
        }

        __syncthreads();
    }

    // ---- rowsum butterfly within each 4-lane quad ----
    rsum0 += __shfl_xor_sync(0xFFFFFFFF, rsum0, 1);
    rsum0 += __shfl_xor_sync(0xFFFFFFFF, rsum0, 2);
    rsum1 += __shfl_xor_sync(0xFFFFFFFF, rsum1, 1);
    rsum1 += __shfl_xor_sync(0xFFFFFFFF, rsum1, 2);
    const float inv0 = 1.0f / rsum0;
    const float inv1 = 1.0f / rsum1;
    if (tg == 0) {
        g_inv_rowsum[(size_t)bh * SSEQ + r0]     = inv0;
        g_inv_rowsum[(size_t)bh * SSEQ + r0 + 8] = inv1;
    }

    // ---- normalized out ----
    float* o0p = out + ((size_t)bh * SSEQ + r0) * DDIM;
    float* o1p = o0p + (size_t)8 * DDIM;
    #pragma unroll
    for (int jn = 0; jn < 16; jn++) {
        const int c = jn * 8 + tg * 2;
        *(float2*)(o0p + c) = make_float2(o[jn][0] * inv0, o[jn][1] * inv0);
        *(float2*)(o1p + c) = make_float2(o[jn][2] * inv1, o[jn][3] * inv1);
    }
}

// Normalize attn in-place: attn[row][*] *= inv_rowsum[row]
__global__ __launch_bounds__(256)
void attn_norm(float* __restrict__ attn)
{
    const size_t total4 = (size_t)BB * HH * SSEQ * SSEQ / 4;
    size_t idx = (size_t)blockIdx.x * blockDim.x + threadIdx.x;
    if (idx >= total4) return;
    size_t base = idx * 4;
    size_t row = base >> 11;
    float inv = g_inv_rowsum[row];
    float4 vv = *(float4*)(attn + base);
    vv.x *= inv; vv.y *= inv; vv.z *= inv; vv.w *= inv;
    *(float4*)(attn + base) = vv;
}

extern "C" void kernel_launch(void* const* d_in, const int* in_sizes, int n_in,
                              void* d_out, int out_size)
{
    const float* q    = (const float*)d_in[0];
    const float* k    = (const float*)d_in[1];
    const float* v    = (const float*)d_in[2];
    const int*   mask = (const int*)d_in[3];

    float* out  = (float*)d_out;
    float* attn = out + (size_t)BB * HH * SSEQ * DDIM;

    cudaFuncSetAttribute(attn_mma, cudaFuncAttributeMaxDynamicSharedMemorySize, SMEM_BYTES);

    dim3 grid(HH, SSEQ / BM, BB);       // h fastest: concurrent CTAs share mask + K/V in L2
    attn_mma<<<grid, NTH, SMEM_BYTES>>>(q, k, v, mask, out, attn);

    size_t total4 = (size_t)BB * HH * SSEQ * SSEQ / 4;
    unsigned blocks = (unsigned)((total4 + 255) / 256);
    attn_norm<<<blocks, 256>>>(attn);
}

// round 8
// speedup vs baseline: 1.0316x; 1.0316x over previous
#include <cuda_runtime.h>
#include <cuda_bf16.h>
#include <cstdint>

#define BB 4
#define HH 16
#define SSEQ 2048
#define DDIM 128
#define BM 128
#define BN 64
#define NTILES (SSEQ / BN)
#define NTH 256

__device__ float g_inv_rowsum[BB * HH * SSEQ];

// smem word layout (uint32 words, each = 2 bf16). Row stride 136 bf16 = 272 B.
#define QST 136
#define QROWW 68
#define Q_HI_W 0
#define Q_LO_W (128 * QROWW)
#define KBUF_HI_W(buf) (17408 + (buf) * 8704)
#define KBUF_LO_W(buf) (KBUF_HI_W(buf) + 4352)
#define VBUF_HI_W(buf) (34816 + (buf) * 8704)
#define VBUF_LO_W(buf) (VBUF_HI_W(buf) + 4352)
#define SMEM_WORDS 52224
#define SMEM_BYTES (SMEM_WORDS * 4)    // 208,896 B

__device__ __forceinline__ uint32_t smem_u32(const void* p) {
    uint32_t a;
    asm("{ .reg .u64 t; cvta.to.shared.u64 t, %1; cvt.u32.u64 %0, t; }" : "=r"(a) : "l"(p));
    return a;
}

__device__ __forceinline__ void mma_bf16(float c[4],
                                         uint32_t a0, uint32_t a1, uint32_t a2, uint32_t a3,
                                         uint32_t b0, uint32_t b1)
{
    asm volatile(
        "mma.sync.aligned.m16n8k16.row.col.f32.bf16.bf16.f32 "
        "{%0,%1,%2,%3}, {%4,%5,%6,%7}, {%8,%9}, {%0,%1,%2,%3};"
        : "+f"(c[0]), "+f"(c[1]), "+f"(c[2]), "+f"(c[3])
        : "r"(a0), "r"(a1), "r"(a2), "r"(a3), "r"(b0), "r"(b1));
}

__device__ __forceinline__ void ldsm4(uint32_t& r0, uint32_t& r1, uint32_t& r2, uint32_t& r3,
                                      uint32_t saddr)
{
    asm volatile("ldmatrix.sync.aligned.m8n8.x4.shared.b16 {%0,%1,%2,%3}, [%4];"
                 : "=r"(r0), "=r"(r1), "=r"(r2), "=r"(r3) : "r"(saddr));
}
__device__ __forceinline__ void ldsm4t(uint32_t& r0, uint32_t& r1, uint32_t& r2, uint32_t& r3,
                                       uint32_t saddr)
{
    asm volatile("ldmatrix.sync.aligned.m8n8.x4.trans.shared.b16 {%0,%1,%2,%3}, [%4];"
                 : "=r"(r0), "=r"(r1), "=r"(r2), "=r"(r3) : "r"(saddr));
}

__device__ __forceinline__ uint32_t prmt7632(uint32_t a, uint32_t b)
{
    uint32_t d;
    asm("prmt.b32 %0, %1, %2, 0x7632;" : "=r"(d) : "r"(a), "r"(b));
    return d;
}

// truncation-based fp32 pair -> bf16 hi/lo split (x0 in low half). ~6 instr.
__device__ __forceinline__ void split2t(float x0, float x1, uint32_t& hi, uint32_t& lo)
{
    uint32_t i0 = __float_as_uint(x0), i1 = __float_as_uint(x1);
    hi = prmt7632(i0, i1);
    float l0 = x0 - __uint_as_float(i0 & 0xFFFF0000u);
    float l1 = x1 - __uint_as_float(i1 & 0xFFFF0000u);
    lo = prmt7632(__float_as_uint(l0), __float_as_uint(l1));
}

// register-resident staging: 8 float4 per thread = one 64x128 fp32 tile per CTA
__device__ __forceinline__ void load8(const float4* p4, int tid, float4 r[8])
{
    #pragma unroll
    for (int it = 0; it < 8; it++) r[it] = p4[it * NTH + tid];
}
__device__ __forceinline__ void store8(const float4 r[8], uint32_t* hi, uint32_t* lo, int tid)
{
    #pragma unroll
    for (int it = 0; it < 8; it++) {
        int idx = it * NTH + tid;
        int row = idx >> 5;
        int c4  = (idx & 31) << 2;
        int w   = (row * QST + c4) >> 1;
        uint32_t h0, l0, h1, l1;
        split2t(r[it].x, r[it].y, h0, l0);
        split2t(r[it].z, r[it].w, h1, l1);
        *(uint2*)(hi + w) = make_uint2(h0, h1);
        *(uint2*)(lo + w) = make_uint2(l0, l1);
    }
}

__global__ __launch_bounds__(NTH, 1)
void attn_mma(const float* __restrict__ q,
              const float* __restrict__ k,
              const float* __restrict__ v,
              const int*   __restrict__ mask,
              float* __restrict__ out,
              float* __restrict__ attn)
{
    extern __shared__ uint32_t SW[];
    const uint32_t sb = smem_u32(SW);

    const int tid  = threadIdx.x;
    const int lane = tid & 31;
    const int w16  = (tid >> 5) * 16;
    const int g    = lane >> 2;
    const int tg   = lane & 3;

    const int h      = blockIdx.x;
    const int qblock = blockIdx.y;
    const int b      = blockIdx.z;
    const int bh     = b * HH + h;
    const int q0     = qblock * BM;
    const size_t head = (size_t)bh * SSEQ * DDIM;

    // ---- stage Q tile (128x128) bf16 hi/lo ----
    {
        const float4* qp4 = (const float4*)(q + head + (size_t)q0 * DDIM);
        #pragma unroll
        for (int it = 0; it < 16; it++) {
            int idx = it * NTH + tid;
            int row = idx >> 5;
            int c4  = (idx & 31) << 2;
            float4 x = qp4[idx];
            uint32_t h0, l0, h1, l1;
            split2t(x.x, x.y, h0, l0);
            split2t(x.z, x.w, h1, l1);
            int w = (row * QST + c4) >> 1;
            *(uint2*)(SW + Q_HI_W + w) = make_uint2(h0, h1);
            *(uint2*)(SW + Q_LO_W + w) = make_uint2(l0, l1);
        }
    }
    // stage K/V tile 0 into buffer 0
    {
        float4 r[8];
        load8((const float4*)(k + head), tid, r);
        store8(r, SW + KBUF_HI_W(0), SW + KBUF_LO_W(0), tid);
        load8((const float4*)(v + head), tid, r);
        store8(r, SW + VBUF_HI_W(0), SW + VBUF_LO_W(0), tid);
    }

    // ldmatrix lane-address bases (byte offsets within a tile)
    const uint32_t a_byte  = (uint32_t)(((w16 + (lane & 15)) * QST + ((lane & 16) ? 8 : 0)) * 2);
    const uint32_t qhi_ad  = sb + Q_HI_W * 4 + a_byte;
    const uint32_t qlo_ad  = sb + Q_LO_W * 4 + a_byte;
    const uint32_t bk_byte = (uint32_t)((((lane & 7) + ((lane & 16) ? 8 : 0)) * QST +
                                         ((lane & 8) ? 8 : 0)) * 2);
    const uint32_t bv_byte = (uint32_t)((((lane & 7) + ((lane & 8) ? 8 : 0)) * QST) * 2 +
                                        ((lane & 16) ? 16 : 0));

    // accumulators
    float o[16][4];
    #pragma unroll
    for (int jn = 0; jn < 16; jn++)
        #pragma unroll
        for (int p = 0; p < 4; p++) o[jn][p] = 0.f;
    float rsum0 = 0.f, rsum1 = 0.f;

    const float scale = 0.08838834764831843f;   // 1/sqrt(128)
    const int r0 = q0 + w16 + g;
    const int* m0p = mask + ((size_t)b * SSEQ + r0) * SSEQ;
    const int* m1p = m0p + (size_t)8 * SSEQ;
    float* a0p = attn + ((size_t)bh * SSEQ + r0) * SSEQ;
    float* a1p = a0p + (size_t)8 * SSEQ;

    __syncthreads();

    for (int kb = 0; kb < NTILES; kb++) {
        const int buf = kb & 1;
        const int k0  = kb * BN;
        const bool pf = (kb + 1 < NTILES);
        const size_t nk0 = (size_t)(k0 + BN) * DDIM;

        // ---- issue next-tile K loads now; consumed AFTER score MMAs ----
        float4 streg[8];
        if (pf) load8((const float4*)(k + head + nk0), tid, streg);

        const uint32_t khi_ad = sb + KBUF_HI_W(buf) * 4 + bk_byte;
        const uint32_t klo_ad = sb + KBUF_LO_W(buf) * 4 + bk_byte;
        const uint32_t vhi_ad = sb + VBUF_HI_W(buf) * 4 + bv_byte;
        const uint32_t vlo_ad = sb + VBUF_LO_W(buf) * 4 + bv_byte;

        // ---- score GEMM: sc[16][64] = Q K^T, 3-way bf16 split ----
        float sc[8][4];
        #pragma unroll
        for (int j = 0; j < 8; j++)
            #pragma unroll
            for (int p = 0; p < 4; p++) sc[j][p] = 0.f;

        #pragma unroll
        for (int ks = 0; ks < 8; ks++) {
            uint32_t ah0, ah1, ah2, ah3, al0, al1, al2, al3;
            ldsm4(ah0, ah1, ah2, ah3, qhi_ad + ks * 32);
            ldsm4(al0, al1, al2, al3, qlo_ad + ks * 32);
            #pragma unroll
            for (int jp = 0; jp < 4; jp++) {
                uint32_t b0, b1, b2, b3, c0, c1, c2, c3;
                ldsm4(b0, b1, b2, b3, khi_ad + ks * 32 + jp * (16 * QST * 2));
                ldsm4(c0, c1, c2, c3, klo_ad + ks * 32 + jp * (16 * QST * 2));
                mma_bf16(sc[2 * jp],     ah0, ah1, ah2, ah3, b0, b1);
                mma_bf16(sc[2 * jp],     ah0, ah1, ah2, ah3, c0, c1);
                mma_bf16(sc[2 * jp],     al0, al1, al2, al3, b0, b1);
                mma_bf16(sc[2 * jp + 1], ah0, ah1, ah2, ah3, b2, b3);
                mma_bf16(sc[2 * jp + 1], ah0, ah1, ah2, ah3, c2, c3);
                mma_bf16(sc[2 * jp + 1], al0, al1, al2, al3, b2, b3);
            }
        }

        // ---- K(next): convert + store to other buffer (LDG latency hidden) ----
        if (pf) store8(streg, SW + KBUF_HI_W(buf ^ 1), SW + KBUF_LO_W(buf ^ 1), tid);

        // ---- issue next-tile V loads; consumed AFTER PV MMAs ----
        if (pf) load8((const float4*)(v + head + nk0), tid, streg);

        // ---- fused epilogue + PV GEMM, per 16-key chunk ----
        // chunk ks: epilogue of score cols j=2ks,2ks+1 -> eh/el[0..3] -> 48 PV MMAs.
        // MUFU/STG/pack of chunk ks+1 issue under the tensor pipe running chunk ks.
        #pragma unroll
        for (int ks = 0; ks < 4; ks++) {
            uint32_t eh[4], el[4];
            #pragma unroll
            for (int jj = 0; jj < 2; jj++) {
                const int j = ks * 2 + jj;
                const int c = k0 + tg * 2 + j * 8;
                int2 m0 = *(const int2*)(m0p + c);
                int2 m1 = *(const int2*)(m1p + c);
                float e00 = m0.x ? __expf(sc[j][0] * scale) : 0.f;
                float e01 = m0.y ? __expf(sc[j][1] * scale) : 0.f;
                float e10 = m1.x ? __expf(sc[j][2] * scale) : 0.f;
                float e11 = m1.y ? __expf(sc[j][3] * scale) : 0.f;
                *(float2*)(a0p + c) = make_float2(e00, e01);
                *(float2*)(a1p + c) = make_float2(e10, e11);
                rsum0 += e00 + e01;
                rsum1 += e10 + e11;
                split2t(e00, e01, eh[jj * 2], el[jj * 2]);
                split2t(e10, e11, eh[jj * 2 + 1], el[jj * 2 + 1]);
            }
            #pragma unroll
            for (int jnp = 0; jnp < 8; jnp++) {
                uint32_t b0, b1, b2, b3, c0, c1, c2, c3;
                ldsm4t(b0, b1, b2, b3, vhi_ad + ks * (16 * QST * 2) + jnp * 32);
                ldsm4t(c0, c1, c2, c3, vlo_ad + ks * (16 * QST * 2) + jnp * 32);
                mma_bf16(o[2 * jnp],     eh[0], eh[1], eh[2], eh[3], b0, b1);
                mma_bf16(o[2 * jnp],     eh[0], eh[1], eh[2], eh[3], c0, c1);
                mma_bf16(o[2 * jnp],     el[0], el[1], el[2], el[3], b0, b1);
                mma_bf16(o[2 * jnp + 1], eh[0], eh[1], eh[2], eh[3], b2, b3);
                mma_bf16(o[2 * jnp + 1], eh[0], eh[1], eh[2], eh[3], c2, c3);
                mma_bf16(o[2 * jnp + 1], el[0], el[1], el[2], el[3], b2, b3);
            }
        }

        // ---- V(next): convert + store (LDG latency hidden behind PV) ----
        if (pf) store8(streg, SW + VBUF_HI_W(buf ^ 1), SW + VBUF_LO_W(buf ^ 1), tid);

        __syncthreads();
    }

    // ---- rowsum butterfly within each 4-lane quad ----
    rsum0 += __shfl_xor_sync(0xFFFFFFFF, rsum0, 1);
    rsum0 += __shfl_xor_sync(0xFFFFFFFF, rsum0, 2);
    rsum1 += __shfl_xor_sync(0xFFFFFFFF, rsum1, 1);
    rsum1 += __shfl_xor_sync(0xFFFFFFFF, rsum1, 2);
    const float inv0 = 1.0f / rsum0;
    const float inv1 = 1.0f / rsum1;
    if (tg == 0) {
        g_inv_rowsum[(size_t)bh * SSEQ + r0]     = inv0;
        g_inv_rowsum[(size_t)bh * SSEQ + r0 + 8] = inv1;
    }

    // ---- normalized out ----
    float* o0p = out + ((size_t)bh * SSEQ + r0) * DDIM;
    float* o1p = o0p + (size_t)8 * DDIM;
    #pragma unroll
    for (int jn = 0; jn < 16; jn++) {
        const int c = jn * 8 + tg * 2;
        *(float2*)(o0p + c) = make_float2(o[jn][0] * inv0, o[jn][1] * inv0);
        *(float2*)(o1p + c) = make_float2(o[jn][2] * inv1, o[jn][3] * inv1);
    }
}

// Normalize attn in-place: attn[row][*] *= inv_rowsum[row]
__global__ __launch_bounds__(256)
void attn_norm(float* __restrict__ attn)
{
    const size_t total4 = (size_t)BB * HH * SSEQ * SSEQ / 4;
    size_t idx = (size_t)blockIdx.x * blockDim.x + threadIdx.x;
    if (idx >= total4) return;
    size_t base = idx * 4;
    size_t row = base >> 11;
    float inv = g_inv_rowsum[row];
    float4 vv = *(float4*)(attn + base);
    vv.x *= inv; vv.y *= inv; vv.z *= inv; vv.w *= inv;
    *(float4*)(attn + base) = vv;
}

extern "C" void kernel_launch(void* const* d_in, const int* in_sizes, int n_in,
                              void* d_out, int out_size)
{
    const float* q    = (const float*)d_in[0];
    const float* k    = (const float*)d_in[1];
    const float* v    = (const float*)d_in[2];
    const int*   mask = (const int*)d_in[3];

    float* out  = (float*)d_out;
    float* attn = out + (size_t)BB * HH * SSEQ * DDIM;

    cudaFuncSetAttribute(attn_mma, cudaFuncAttributeMaxDynamicSharedMemorySize, SMEM_BYTES);

    dim3 grid(HH, SSEQ / BM, BB);       // h fastest: concurrent CTAs share mask + K/V in L2
    attn_mma<<<grid, NTH, SMEM_BYTES>>>(q, k, v, mask, out, attn);

    size_t total4 = (size_t)BB * HH * SSEQ * SSEQ / 4;
    unsigned blocks = (unsigned)((total4 + 255) / 256);
    attn_norm<<<blocks, 256>>>(attn);
}

// round 9
// speedup vs baseline: 1.0567x; 1.0243x over previous
#include <cuda_runtime.h>
#include <cuda_bf16.h>
#include <cstdint>

#define BB 4
#define HH 16
#define SSEQ 2048
#define DDIM 128
#define BM 128
#define BN 64
#define NTILES (SSEQ / BN)
#define NTH 256
#define N4PLANE (BB * HH * SSEQ * DDIM / 4)   // float4 count per plane

__device__ float g_inv_rowsum[BB * HH * SSEQ];
// precomputed bf16 hi/lo planes for K and V (row-major, same indexing as inputs)
__device__ uint2 g_kh[N4PLANE], g_kl[N4PLANE], g_vh[N4PLANE], g_vl[N4PLANE];

// smem word layout (uint32 words, each = 2 bf16). Row stride 136 bf16 = 272 B.
#define QST 136
#define QROWW 68
#define Q_HI_W 0
#define Q_LO_W (128 * QROWW)
#define KBUF_HI_W(buf) (17408 + (buf) * 8704)
#define KBUF_LO_W(buf) (KBUF_HI_W(buf) + 4352)
#define VBUF_HI_W(buf) (34816 + (buf) * 8704)
#define VBUF_LO_W(buf) (VBUF_HI_W(buf) + 4352)
#define SMEM_WORDS 52224
#define SMEM_BYTES (SMEM_WORDS * 4)    // 208,896 B

__device__ __forceinline__ uint32_t smem_u32(const void* p) {
    uint32_t a;
    asm("{ .reg .u64 t; cvta.to.shared.u64 t, %1; cvt.u32.u64 %0, t; }" : "=r"(a) : "l"(p));
    return a;
}

__device__ __forceinline__ void mma_bf16(float c[4],
                                         uint32_t a0, uint32_t a1, uint32_t a2, uint32_t a3,
                                         uint32_t b0, uint32_t b1)
{
    asm volatile(
        "mma.sync.aligned.m16n8k16.row.col.f32.bf16.bf16.f32 "
        "{%0,%1,%2,%3}, {%4,%5,%6,%7}, {%8,%9}, {%0,%1,%2,%3};"
        : "+f"(c[0]), "+f"(c[1]), "+f"(c[2]), "+f"(c[3])
        : "r"(a0), "r"(a1), "r"(a2), "r"(a3), "r"(b0), "r"(b1));
}

__device__ __forceinline__ void ldsm4(uint32_t& r0, uint32_t& r1, uint32_t& r2, uint32_t& r3,
                                      uint32_t saddr)
{
    asm volatile("ldmatrix.sync.aligned.m8n8.x4.shared.b16 {%0,%1,%2,%3}, [%4];"
                 : "=r"(r0), "=r"(r1), "=r"(r2), "=r"(r3) : "r"(saddr));
}
__device__ __forceinline__ void ldsm4t(uint32_t& r0, uint32_t& r1, uint32_t& r2, uint32_t& r3,
                                       uint32_t saddr)
{
    asm volatile("ldmatrix.sync.aligned.m8n8.x4.trans.shared.b16 {%0,%1,%2,%3}, [%4];"
                 : "=r"(r0), "=r"(r1), "=r"(r2), "=r"(r3) : "r"(saddr));
}

#define CP16(dst, src) \
    asm volatile("cp.async.cg.shared.global [%0], [%1], 16;" :: "r"(dst), "l"(src))
#define CP_COMMIT() asm volatile("cp.async.commit_group;" ::: "memory")
#define CP_WAIT0()  asm volatile("cp.async.wait_group 0;" ::: "memory")

__device__ __forceinline__ uint32_t prmt7632(uint32_t a, uint32_t b)
{
    uint32_t d;
    asm("prmt.b32 %0, %1, %2, 0x7632;" : "=r"(d) : "r"(a), "r"(b));
    return d;
}

// rn-based split (accurate; used for precompute + Q)
__device__ __forceinline__ void split2(float x0, float x1, uint32_t& hi, uint32_t& lo)
{
    __nv_bfloat162 h = __floats2bfloat162_rn(x0, x1);
    float2 hf = __bfloat1622float2(h);
    __nv_bfloat162 l = __floats2bfloat162_rn(x0 - hf.x, x1 - hf.y);
    hi = *reinterpret_cast<uint32_t*>(&h);
    lo = *reinterpret_cast<uint32_t*>(&l);
}
// truncation-based split (cheap; used for e in the hot loop)
__device__ __forceinline__ void split2t(float x0, float x1, uint32_t& hi, uint32_t& lo)
{
    uint32_t i0 = __float_as_uint(x0), i1 = __float_as_uint(x1);
    hi = prmt7632(i0, i1);
    float l0 = x0 - __uint_as_float(i0 & 0xFFFF0000u);
    float l1 = x1 - __uint_as_float(i1 & 0xFFFF0000u);
    lo = prmt7632(__float_as_uint(l0), __float_as_uint(l1));
}

// one-time K/V split kernel: fp32 -> bf16 hi/lo planes
__global__ __launch_bounds__(256)
void conv_kv(const float4* __restrict__ k, const float4* __restrict__ v)
{
    int i = blockIdx.x * blockDim.x + threadIdx.x;
    if (i >= N4PLANE) return;
    float4 x = k[i];
    uint32_t h0, l0, h1, l1;
    split2(x.x, x.y, h0, l0);
    split2(x.z, x.w, h1, l1);
    g_kh[i] = make_uint2(h0, h1);
    g_kl[i] = make_uint2(l0, l1);
    float4 y = v[i];
    split2(y.x, y.y, h0, l0);
    split2(y.z, y.w, h1, l1);
    g_vh[i] = make_uint2(h0, h1);
    g_vl[i] = make_uint2(l0, l1);
}

// issue 16 cp.async per thread: K/V hi+lo tile (64x128 each) into buffer `dstbuf`
__device__ __forceinline__ void cp_tile(uint32_t sb, int dstbuf, size_t base_e, int tid)
{
    #pragma unroll
    for (int i = 0; i < 4; i++) {
        int chunk = i * NTH + tid;                 // 0..1023
        int row = chunk >> 4, c = chunk & 15;
        uint32_t smoff = (uint32_t)(row * 272 + c * 16);
        size_t gb = (base_e + (size_t)row * DDIM + c * 8) * 2;   // byte offset in plane
        CP16(sb + KBUF_HI_W(dstbuf) * 4 + smoff, (const char*)g_kh + gb);
        CP16(sb + KBUF_LO_W(dstbuf) * 4 + smoff, (const char*)g_kl + gb);
        CP16(sb + VBUF_HI_W(dstbuf) * 4 + smoff, (const char*)g_vh + gb);
        CP16(sb + VBUF_LO_W(dstbuf) * 4 + smoff, (const char*)g_vl + gb);
    }
}

__global__ __launch_bounds__(NTH, 1)
void attn_mma(const float* __restrict__ q,
              const int*   __restrict__ mask,
              float* __restrict__ out,
              float* __restrict__ attn)
{
    extern __shared__ uint32_t SW[];
    const uint32_t sb = smem_u32(SW);

    const int tid  = threadIdx.x;
    const int lane = tid & 31;
    const int w16  = (tid >> 5) * 16;
    const int g    = lane >> 2;
    const int tg   = lane & 3;

    const int h      = blockIdx.x;
    const int qblock = blockIdx.y;
    const int b      = blockIdx.z;
    const int bh     = b * HH + h;
    const int q0     = qblock * BM;
    const size_t head = (size_t)bh * SSEQ * DDIM;

    // ---- async-stage K/V tile 0 ----
    cp_tile(sb, 0, head, tid);
    CP_COMMIT();

    // ---- stage Q tile (128x128) bf16 hi/lo (once per CTA, rn split) ----
    {
        const float4* qp4 = (const float4*)(q + head + (size_t)q0 * DDIM);
        #pragma unroll
        for (int it = 0; it < 16; it++) {
            int idx = it * NTH + tid;
            int row = idx >> 5;
            int c4  = (idx & 31) << 2;
            float4 x = qp4[idx];
            uint32_t h0, l0, h1, l1;
            split2(x.x, x.y, h0, l0);
            split2(x.z, x.w, h1, l1);
            int w = (row * QST + c4) >> 1;
            *(uint2*)(SW + Q_HI_W + w) = make_uint2(h0, h1);
            *(uint2*)(SW + Q_LO_W + w) = make_uint2(l0, l1);
        }
    }

    // ldmatrix lane-address bases (byte offsets within a tile)
    const uint32_t a_byte  = (uint32_t)(((w16 + (lane & 15)) * QST + ((lane & 16) ? 8 : 0)) * 2);
    const uint32_t qhi_ad  = sb + Q_HI_W * 4 + a_byte;
    const uint32_t qlo_ad  = sb + Q_LO_W * 4 + a_byte;
    const uint32_t bk_byte = (uint32_t)((((lane & 7) + ((lane & 16) ? 8 : 0)) * QST +
                                         ((lane & 8) ? 8 : 0)) * 2);
    const uint32_t bv_byte = (uint32_t)((((lane & 7) + ((lane & 8) ? 8 : 0)) * QST) * 2 +
                                        ((lane & 16) ? 16 : 0));

    // accumulators
    float o[16][4];
    #pragma unroll
    for (int jn = 0; jn < 16; jn++)
        #pragma unroll
        for (int p = 0; p < 4; p++) o[jn][p] = 0.f;
    float rsum0 = 0.f, rsum1 = 0.f;

    const float scale = 0.08838834764831843f;   // 1/sqrt(128)
    const int r0 = q0 + w16 + g;
    const int* m0p = mask + ((size_t)b * SSEQ + r0) * SSEQ;
    const int* m1p = m0p + (size_t)8 * SSEQ;
    float* a0p = attn + ((size_t)bh * SSEQ + r0) * SSEQ;
    float* a1p = a0p + (size_t)8 * SSEQ;

    CP_WAIT0();
    __syncthreads();

    for (int kb = 0; kb < NTILES; kb++) {
        const int buf = kb & 1;
        const int k0  = kb * BN;
        const bool pf = (kb + 1 < NTILES);

        // ---- async-stage next tile into other buffer (completes by end of this tile) ----
        if (pf) {
            cp_tile(sb, buf ^ 1, head + (size_t)(k0 + BN) * DDIM, tid);
            CP_COMMIT();
        }

        const uint32_t khi_ad = sb + KBUF_HI_W(buf) * 4 + bk_byte;
        const uint32_t klo_ad = sb + KBUF_LO_W(buf) * 4 + bk_byte;
        const uint32_t vhi_ad = sb + VBUF_HI_W(buf) * 4 + bv_byte;
        const uint32_t vlo_ad = sb + VBUF_LO_W(buf) * 4 + bv_byte;

        // ---- score GEMM: sc[16][64] = Q K^T; MMAs grouped by split term so each
        //      accumulator is touched at distance 8 (no RAW stall on HMMA latency) ----
        float sc[8][4];
        #pragma unroll
        for (int j = 0; j < 8; j++)
            #pragma unroll
            for (int p = 0; p < 4; p++) sc[j][p] = 0.f;

        #pragma unroll
        for (int ks = 0; ks < 8; ks++) {
            uint32_t ah0, ah1, ah2, ah3, al0, al1, al2, al3;
            ldsm4(ah0, ah1, ah2, ah3, qhi_ad + ks * 32);
            ldsm4(al0, al1, al2, al3, qlo_ad + ks * 32);
            uint32_t bhf[4][4], blf[4][4];
            #pragma unroll
            for (int jp = 0; jp < 4; jp++) {
                ldsm4(bhf[jp][0], bhf[jp][1], bhf[jp][2], bhf[jp][3],
                      khi_ad + ks * 32 + jp * (16 * QST * 2));
                ldsm4(blf[jp][0], blf[jp][1], blf[jp][2], blf[jp][3],
                      klo_ad + ks * 32 + jp * (16 * QST * 2));
            }
            #pragma unroll
            for (int jp = 0; jp < 4; jp++) {        // term hh
                mma_bf16(sc[2 * jp],     ah0, ah1, ah2, ah3, bhf[jp][0], bhf[jp][1]);
                mma_bf16(sc[2 * jp + 1], ah0, ah1, ah2, ah3, bhf[jp][2], bhf[jp][3]);
            }
            #pragma unroll
            for (int jp = 0; jp < 4; jp++) {        // term hl
                mma_bf16(sc[2 * jp],     ah0, ah1, ah2, ah3, blf[jp][0], blf[jp][1]);
                mma_bf16(sc[2 * jp + 1], ah0, ah1, ah2, ah3, blf[jp][2], blf[jp][3]);
            }
            #pragma unroll
            for (int jp = 0; jp < 4; jp++) {        // term lh
                mma_bf16(sc[2 * jp],     al0, al1, al2, al3, bhf[jp][0], bhf[jp][1]);
                mma_bf16(sc[2 * jp + 1], al0, al1, al2, al3, bhf[jp][2], bhf[jp][3]);
            }
        }

        // ---- epilogue: mask + exp, write unnormalized attn, pack e hi/lo ----
        uint32_t eh[16], el[16];
        #pragma unroll
        for (int j = 0; j < 8; j++) {
            const int c = k0 + tg * 2 + j * 8;
            int2 m0 = *(const int2*)(m0p + c);
            int2 m1 = *(const int2*)(m1p + c);
            float e00 = m0.x ? __expf(sc[j][0] * scale) : 0.f;
            float e01 = m0.y ? __expf(sc[j][1] * scale) : 0.f;
            float e10 = m1.x ? __expf(sc[j][2] * scale) : 0.f;
            float e11 = m1.y ? __expf(sc[j][3] * scale) : 0.f;
            *(float2*)(a0p + c) = make_float2(e00, e01);
            *(float2*)(a1p + c) = make_float2(e10, e11);
            rsum0 += e00 + e01;
            rsum1 += e10 + e11;
            split2t(e00, e01, eh[j * 2], el[j * 2]);
            split2t(e10, e11, eh[j * 2 + 1], el[j * 2 + 1]);
        }

        // ---- PV GEMM: o[16][128] += e[16x64] * V[64x128]; same distance-8 grouping ----
        #pragma unroll
        for (int ks = 0; ks < 4; ks++) {
            uint32_t ah0 = eh[ks * 4 + 0], ah1 = eh[ks * 4 + 1];
            uint32_t ah2 = eh[ks * 4 + 2], ah3 = eh[ks * 4 + 3];
            uint32_t al0 = el[ks * 4 + 0], al1 = el[ks * 4 + 1];
            uint32_t al2 = el[ks * 4 + 2], al3 = el[ks * 4 + 3];
            #pragma unroll
            for (int gjn = 0; gjn < 2; gjn++) {
                uint32_t vhf[4][4], vlf[4][4];
                #pragma unroll
                for (int j = 0; j < 4; j++) {
                    int jnp = gjn * 4 + j;
                    ldsm4t(vhf[j][0], vhf[j][1], vhf[j][2], vhf[j][3],
                           vhi_ad + ks * (16 * QST * 2) + jnp * 32);
                    ldsm4t(vlf[j][0], vlf[j][1], vlf[j][2], vlf[j][3],
                           vlo_ad + ks * (16 * QST * 2) + jnp * 32);
                }
                #pragma unroll
                for (int j = 0; j < 4; j++) {       // term hh
                    int jnp = gjn * 4 + j;
                    mma_bf16(o[2 * jnp],     ah0, ah1, ah2, ah3, vhf[j][0], vhf[j][1]);
                    mma_bf16(o[2 * jnp + 1], ah0, ah1, ah2, ah3, vhf[j][2], vhf[j][3]);
                }
                #pragma unroll
                for (int j = 0; j < 4; j++) {       // term hl
                    int jnp = gjn * 4 + j;
                    mma_bf16(o[2 * jnp],     ah0, ah1, ah2, ah3, vlf[j][0], vlf[j][1]);
                    mma_bf16(o[2 * jnp + 1], ah0, ah1, ah2, ah3, vlf[j][2], vlf[j][3]);
                }
                #pragma unroll
                for (int j = 0; j < 4; j++) {       // term lh
                    int jnp = gjn * 4 + j;
                    mma_bf16(o[2 * jnp],     al0, al1, al2, al3, vhf[j][0], vhf[j][1]);
                    mma_bf16(o[2 * jnp + 1], al0, al1, al2, al3, vhf[j][2], vhf[j][3]);
                }
            }
        }

        if (pf) CP_WAIT0();
        __syncthreads();
    }

    // ---- rowsum butterfly within each 4-lane quad ----
    rsum0 += __shfl_xor_sync(0xFFFFFFFF, rsum0, 1);
    rsum0 += __shfl_xor_sync(0xFFFFFFFF, rsum0, 2);
    rsum1 += __shfl_xor_sync(0xFFFFFFFF, rsum1, 1);
    rsum1 += __shfl_xor_sync(0xFFFFFFFF, rsum1, 2);
    const float inv0 = 1.0f / rsum0;
    const float inv1 = 1.0f / rsum1;
    if (tg == 0) {
        g_inv_rowsum[(size_t)bh * SSEQ + r0]     = inv0;
        g_inv_rowsum[(size_t)bh * SSEQ + r0 + 8] = inv1;
    }

    // ---- normalized out ----
    float* o0p = out + ((size_t)bh * SSEQ + r0) * DDIM;
    float* o1p = o0p + (size_t)8 * DDIM;
    #pragma unroll
    for (int jn = 0; jn < 16; jn++) {
        const int c = jn * 8 + tg * 2;
        *(float2*)(o0p + c) = make_float2(o[jn][0] * inv0, o[jn][1] * inv0);
        *(float2*)(o1p + c) = make_float2(o[jn][2] * inv1, o[jn][3] * inv1);
    }
}

// Normalize attn in-place: attn[row][*] *= inv_rowsum[row]
__global__ __launch_bounds__(256)
void attn_norm(float* __restrict__ attn)
{
    const size_t total4 = (size_t)BB * HH * SSEQ * SSEQ / 4;
    size_t idx = (size_t)blockIdx.x * blockDim.x + threadIdx.x;
    if (idx >= total4) return;
    size_t base = idx * 4;
    size_t row = base >> 11;
    float inv = g_inv_rowsum[row];
    float4 vv = *(float4*)(attn + base);
    vv.x *= inv; vv.y *= inv; vv.z *= inv; vv.w *= inv;
    *(float4*)(attn + base) = vv;
}

extern "C" void kernel_launch(void* const* d_in, const int* in_sizes, int n_in,
                              void* d_out, int out_size)
{
    const float* q    = (const float*)d_in[0];
    const float* k    = (const float*)d_in[1];
    const float* v    = (const float*)d_in[2];
    const int*   mask = (const int*)d_in[3];

    float* out  = (float*)d_out;
    float* attn = out + (size_t)BB * HH * SSEQ * DDIM;

    // one-time (per launch) K/V bf16 hi/lo split into gmem planes
    conv_kv<<<N4PLANE / 256, 256>>>((const float4*)k, (const float4*)v);

    cudaFuncSetAttribute(attn_mma, cudaFuncAttributeMaxDynamicSharedMemorySize, SMEM_BYTES);
    dim3 grid(HH, SSEQ / BM, BB);       // h fastest: concurrent CTAs share mask + K/V in L2
    attn_mma<<<grid, NTH, SMEM_BYTES>>>(q, mask, out, attn);

    size_t total4 = (size_t)BB * HH * SSEQ * SSEQ / 4;
    unsigned blocks = (unsigned)((total4 + 255) / 256);
    attn_norm<<<blocks, 256>>>(attn);
}

// round 10
// speedup vs baseline: 1.3341x; 1.2625x over previous
#include <cuda_runtime.h>
#include <cuda_fp16.h>
#include <cstdint>

#define BB 4
#define HH 16
#define SSEQ 2048
#define DDIM 128
#define BM 128
#define BN 64
#define NTILES (SSEQ / BN)
#define NTH 256
#define N4PLANE (BB * HH * SSEQ * DDIM / 4)   // uint2 (4 fp16) count per plane

__device__ float g_inv_rowsum[BB * HH * SSEQ];
// precomputed single-plane fp16 K and V (row-major, same indexing as inputs)
__device__ uint2 g_kh[N4PLANE], g_vh[N4PLANE];

// smem word layout (uint32 words, each = 2 fp16). Row stride 136 elems = 272 B.
#define QST 136
#define QROWW 68
#define Q_HI_W 0
#define Q_LO_W (128 * QROWW)                   // 8704
#define KBUF_W(buf) (17408 + (buf) * 4352)
#define VBUF_W(buf) (26112 + (buf) * 4352)
#define SMEM_WORDS 34816
#define SMEM_BYTES (SMEM_WORDS * 4)            // 139,264 B

__device__ __forceinline__ uint32_t smem_u32(const void* p) {
    uint32_t a;
    asm("{ .reg .u64 t; cvta.to.shared.u64 t, %1; cvt.u32.u64 %0, t; }" : "=r"(a) : "l"(p));
    return a;
}

__device__ __forceinline__ void mma_f16(float c[4],
                                        uint32_t a0, uint32_t a1, uint32_t a2, uint32_t a3,
                                        uint32_t b0, uint32_t b1)
{
    asm volatile(
        "mma.sync.aligned.m16n8k16.row.col.f32.f16.f16.f32 "
        "{%0,%1,%2,%3}, {%4,%5,%6,%7}, {%8,%9}, {%0,%1,%2,%3};"
        : "+f"(c[0]), "+f"(c[1]), "+f"(c[2]), "+f"(c[3])
        : "r"(a0), "r"(a1), "r"(a2), "r"(a3), "r"(b0), "r"(b1));
}

__device__ __forceinline__ void ldsm4(uint32_t& r0, uint32_t& r1, uint32_t& r2, uint32_t& r3,
                                      uint32_t saddr)
{
    asm volatile("ldmatrix.sync.aligned.m8n8.x4.shared.b16 {%0,%1,%2,%3}, [%4];"
                 : "=r"(r0), "=r"(r1), "=r"(r2), "=r"(r3) : "r"(saddr));
}
__device__ __forceinline__ void ldsm4t(uint32_t& r0, uint32_t& r1, uint32_t& r2, uint32_t& r3,
                                       uint32_t saddr)
{
    asm volatile("ldmatrix.sync.aligned.m8n8.x4.trans.shared.b16 {%0,%1,%2,%3}, [%4];"
                 : "=r"(r0), "=r"(r1), "=r"(r2), "=r"(r3) : "r"(saddr));
}

#define CP16(dst, src) \
    asm volatile("cp.async.cg.shared.global [%0], [%1], 16;" :: "r"(dst), "l"(src))
#define CP_COMMIT() asm volatile("cp.async.commit_group;" ::: "memory")
#define CP_WAIT0()  asm volatile("cp.async.wait_group 0;" ::: "memory")

// fp32 pair -> fp16 hi/lo 2-term split, packed half2 words (x0 in low half)
__device__ __forceinline__ void split2h(float x0, float x1, uint32_t& hi, uint32_t& lo)
{
    __half2 h = __floats2half2_rn(x0, x1);
    float2 hf = __half22float2(h);
    __half2 l = __floats2half2_rn(x0 - hf.x, x1 - hf.y);
    hi = *reinterpret_cast<uint32_t*>(&h);
    lo = *reinterpret_cast<uint32_t*>(&l);
}

// one-time K/V conversion: fp32 -> single fp16 plane each
__global__ __launch_bounds__(256)
void conv_kv(const float4* __restrict__ k, const float4* __restrict__ v)
{
    int i = blockIdx.x * blockDim.x + threadIdx.x;
    if (i >= N4PLANE) return;
    float4 x = k[i];
    __half2 a = __floats2half2_rn(x.x, x.y);
    __half2 b = __floats2half2_rn(x.z, x.w);
    g_kh[i] = make_uint2(*reinterpret_cast<uint32_t*>(&a), *reinterpret_cast<uint32_t*>(&b));
    float4 y = v[i];
    a = __floats2half2_rn(y.x, y.y);
    b = __floats2half2_rn(y.z, y.w);
    g_vh[i] = make_uint2(*reinterpret_cast<uint32_t*>(&a), *reinterpret_cast<uint32_t*>(&b));
}

// async-stage one K/V fp16 tile (64x128 each) into buffer `dstbuf`: 8 cp.async/thread
__device__ __forceinline__ void cp_tile(uint32_t sb, int dstbuf, size_t base_e, int tid)
{
    #pragma unroll
    for (int i = 0; i < 4; i++) {
        int chunk = i * NTH + tid;                 // 0..1023
        int row = chunk >> 4, c = chunk & 15;
        uint32_t smoff = (uint32_t)(row * 272 + c * 16);
        size_t gb = (base_e + (size_t)row * DDIM + c * 8) * 2;   // bytes into fp16 plane
        CP16(sb + KBUF_W(dstbuf) * 4 + smoff, (const char*)g_kh + gb);
        CP16(sb + VBUF_W(dstbuf) * 4 + smoff, (const char*)g_vh + gb);
    }
}

__global__ __launch_bounds__(NTH, 1)
void attn_mma(const float* __restrict__ q,
              const int*   __restrict__ mask,
              float* __restrict__ out,
              float* __restrict__ attn)
{
    extern __shared__ uint32_t SW[];
    const uint32_t sb = smem_u32(SW);

    const int tid  = threadIdx.x;
    const int lane = tid & 31;
    const int w16  = (tid >> 5) * 16;
    const int g    = lane >> 2;
    const int tg   = lane & 3;

    const int h      = blockIdx.x;
    const int qblock = blockIdx.y;
    const int b      = blockIdx.z;
    const int bh     = b * HH + h;
    const int q0     = qblock * BM;
    const size_t head = (size_t)bh * SSEQ * DDIM;

    // ---- async-stage K/V tile 0 ----
    cp_tile(sb, 0, head, tid);
    CP_COMMIT();

    // ---- stage Q tile (128x128) fp16 hi/lo (2-term split) ----
    {
        const float4* qp4 = (const float4*)(q + head + (size_t)q0 * DDIM);
        #pragma unroll
        for (int it = 0; it < 16; it++) {
            int idx = it * NTH + tid;
            int row = idx >> 5;
            int c4  = (idx & 31) << 2;
            float4 x = qp4[idx];
            uint32_t h0, l0, h1, l1;
            split2h(x.x, x.y, h0, l0);
            split2h(x.z, x.w, h1, l1);
            int w = (row * QST + c4) >> 1;
            *(uint2*)(SW + Q_HI_W + w) = make_uint2(h0, h1);
            *(uint2*)(SW + Q_LO_W + w) = make_uint2(l0, l1);
        }
    }

    // ldmatrix lane-address bases (byte offsets within a tile)
    const uint32_t a_byte  = (uint32_t)(((w16 + (lane & 15)) * QST + ((lane & 16) ? 8 : 0)) * 2);
    const uint32_t qhi_ad  = sb + Q_HI_W * 4 + a_byte;
    const uint32_t qlo_ad  = sb + Q_LO_W * 4 + a_byte;
    const uint32_t bk_byte = (uint32_t)((((lane & 7) + ((lane & 16) ? 8 : 0)) * QST +
                                         ((lane & 8) ? 8 : 0)) * 2);
    const uint32_t bv_byte = (uint32_t)((((lane & 7) + ((lane & 8) ? 8 : 0)) * QST) * 2 +
                                        ((lane & 16) ? 16 : 0));

    // accumulators
    float o[16][4];
    #pragma unroll
    for (int jn = 0; jn < 16; jn++)
        #pragma unroll
        for (int p = 0; p < 4; p++) o[jn][p] = 0.f;
    float rsum0 = 0.f, rsum1 = 0.f;

    const float scale = 0.08838834764831843f;   // 1/sqrt(128)
    const int r0 = q0 + w16 + g;
    const int* m0p = mask + ((size_t)b * SSEQ + r0) * SSEQ;
    const int* m1p = m0p + (size_t)8 * SSEQ;
    float* a0p = attn + ((size_t)bh * SSEQ + r0) * SSEQ;
    float* a1p = a0p + (size_t)8 * SSEQ;

    CP_WAIT0();
    __syncthreads();

    for (int kb = 0; kb < NTILES; kb++) {
        const int buf = kb & 1;
        const int k0  = kb * BN;
        const bool pf = (kb + 1 < NTILES);

        // ---- async-stage next tile; completes by end of this tile ----
        if (pf) {
            cp_tile(sb, buf ^ 1, head + (size_t)(k0 + BN) * DDIM, tid);
            CP_COMMIT();
        }

        // ---- mask prefetch (L2 latency hidden under score MMAs) ----
        int2 mv0[8], mv1[8];
        #pragma unroll
        for (int j = 0; j < 8; j++) {
            const int c = k0 + tg * 2 + j * 8;
            mv0[j] = *(const int2*)(m0p + c);
            mv1[j] = *(const int2*)(m1p + c);
        }

        const uint32_t k_ad = sb + KBUF_W(buf) * 4 + bk_byte;
        const uint32_t v_ad = sb + VBUF_W(buf) * 4 + bv_byte;

        // ---- score GEMM: sc[16][64] = (Qh+Ql) K^T (K single fp16 plane) ----
        float sc[8][4];
        #pragma unroll
        for (int j = 0; j < 8; j++)
            #pragma unroll
            for (int p = 0; p < 4; p++) sc[j][p] = 0.f;

        #pragma unroll
        for (int ks = 0; ks < 8; ks++) {
            uint32_t ah0, ah1, ah2, ah3, al0, al1, al2, al3;
            ldsm4(ah0, ah1, ah2, ah3, qhi_ad + ks * 32);
            ldsm4(al0, al1, al2, al3, qlo_ad + ks * 32);
            uint32_t bf[4][4];
            #pragma unroll
            for (int jp = 0; jp < 4; jp++)
                ldsm4(bf[jp][0], bf[jp][1], bf[jp][2], bf[jp][3],
                      k_ad + ks * 32 + jp * (16 * QST * 2));
            #pragma unroll
            for (int jp = 0; jp < 4; jp++) {        // term: Qhi x K
                mma_f16(sc[2 * jp],     ah0, ah1, ah2, ah3, bf[jp][0], bf[jp][1]);
                mma_f16(sc[2 * jp + 1], ah0, ah1, ah2, ah3, bf[jp][2], bf[jp][3]);
            }
            #pragma unroll
            for (int jp = 0; jp < 4; jp++) {        // term: Qlo x K
                mma_f16(sc[2 * jp],     al0, al1, al2, al3, bf[jp][0], bf[jp][1]);
                mma_f16(sc[2 * jp + 1], al0, al1, al2, al3, bf[jp][2], bf[jp][3]);
            }
        }

        // ---- epilogue: mask + exp, write unnormalized attn, pack e (fp16 2-term) ----
        uint32_t eh[16], el[16];
        #pragma unroll
        for (int j = 0; j < 8; j++) {
            const int c = k0 + tg * 2 + j * 8;
            float e00 = mv0[j].x ? __expf(sc[j][0] * scale) : 0.f;
            float e01 = mv0[j].y ? __expf(sc[j][1] * scale) : 0.f;
            float e10 = mv1[j].x ? __expf(sc[j][2] * scale) : 0.f;
            float e11 = mv1[j].y ? __expf(sc[j][3] * scale) : 0.f;
            *(float2*)(a0p + c) = make_float2(e00, e01);
            *(float2*)(a1p + c) = make_float2(e10, e11);
            rsum0 += e00 + e01;
            rsum1 += e10 + e11;
            split2h(e00, e01, eh[j * 2], el[j * 2]);
            split2h(e10, e11, eh[j * 2 + 1], el[j * 2 + 1]);
        }

        // ---- PV GEMM: o[16][128] += (eh+el) V (V single fp16 plane) ----
        #pragma unroll
        for (int ks = 0; ks < 4; ks++) {
            uint32_t a0 = eh[ks * 4 + 0], a1 = eh[ks * 4 + 1];
            uint32_t a2 = eh[ks * 4 + 2], a3 = eh[ks * 4 + 3];
            uint32_t c0 = el[ks * 4 + 0], c1 = el[ks * 4 + 1];
            uint32_t c2 = el[ks * 4 + 2], c3 = el[ks * 4 + 3];
            #pragma unroll
            for (int gjn = 0; gjn < 2; gjn++) {
                uint32_t vf[4][4];
                #pragma unroll
                for (int j = 0; j < 4; j++) {
                    int jnp = gjn * 4 + j;
                    ldsm4t(vf[j][0], vf[j][1], vf[j][2], vf[j][3],
                           v_ad + ks * (16 * QST * 2) + jnp * 32);
                }
                #pragma unroll
                for (int j = 0; j < 4; j++) {       // term: eh x V
                    int jnp = gjn * 4 + j;
                    mma_f16(o[2 * jnp],     a0, a1, a2, a3, vf[j][0], vf[j][1]);
                    mma_f16(o[2 * jnp + 1], a0, a1, a2, a3, vf[j][2], vf[j][3]);
                }
                #pragma unroll
                for (int j = 0; j < 4; j++) {       // term: el x V
                    int jnp = gjn * 4 + j;
                    mma_f16(o[2 * jnp],     c0, c1, c2, c3, vf[j][0], vf[j][1]);
                    mma_f16(o[2 * jnp + 1], c0, c1, c2, c3, vf[j][2], vf[j][3]);
                }
            }
        }

        if (pf) CP_WAIT0();
        __syncthreads();
    }

    // ---- rowsum butterfly within each 4-lane quad ----
    rsum0 += __shfl_xor_sync(0xFFFFFFFF, rsum0, 1);
    rsum0 += __shfl_xor_sync(0xFFFFFFFF, rsum0, 2);
    rsum1 += __shfl_xor_sync(0xFFFFFFFF, rsum1, 1);
    rsum1 += __shfl_xor_sync(0xFFFFFFFF, rsum1, 2);
    const float inv0 = 1.0f / rsum0;
    const float inv1 = 1.0f / rsum1;
    if (tg == 0) {
        g_inv_rowsum[(size_t)bh * SSEQ + r0]     = inv0;
        g_inv_rowsum[(size_t)bh * SSEQ + r0 + 8] = inv1;
    }

    // ---- normalized out ----
    float* o0p = out + ((size_t)bh * SSEQ + r0) * DDIM;
    float* o1p = o0p + (size_t)8 * DDIM;
    #pragma unroll
    for (int jn = 0; jn < 16; jn++) {
        const int c = jn * 8 + tg * 2;
        *(float2*)(o0p + c) = make_float2(o[jn][0] * inv0, o[jn][1] * inv0);
        *(float2*)(o1p + c) = make_float2(o[jn][2] * inv1, o[jn][3] * inv1);
    }
}

// Normalize attn in-place: attn[row][*] *= inv_rowsum[row]
__global__ __launch_bounds__(256)
void attn_norm(float* __restrict__ attn)
{
    const size_t total4 = (size_t)BB * HH * SSEQ * SSEQ / 4;
    size_t idx = (size_t)blockIdx.x * blockDim.x + threadIdx.x;
    if (idx >= total4) return;
    size_t base = idx * 4;
    size_t row = base >> 11;
    float inv = g_inv_rowsum[row];
    float4 vv = *(float4*)(attn + base);
    vv.x *= inv; vv.y *= inv; vv.z *= inv; vv.w *= inv;
    *(float4*)(attn + base) = vv;
}

extern "C" void kernel_launch(void* const* d_in, const int* in_sizes, int n_in,
                              void* d_out, int out_size)
{
    const float* q    = (const float*)d_in[0];
    const float* k    = (const float*)d_in[1];
    const float* v    = (const float*)d_in[2];
    const int*   mask = (const int*)d_in[3];

    float* out  = (float*)d_out;
    float* attn = out + (size_t)BB * HH * SSEQ * DDIM;

    // one-time (per launch) K/V fp16 conversion into gmem planes
    conv_kv<<<N4PLANE / 256, 256>>>((const float4*)k, (const float4*)v);

    cudaFuncSetAttribute(attn_mma, cudaFuncAttributeMaxDynamicSharedMemorySize, SMEM_BYTES);
    dim3 grid(HH, SSEQ / BM, BB);       // h fastest: concurrent CTAs share mask + K/V in L2
    attn_mma<<<grid, NTH, SMEM_BYTES>>>(q, mask, out, attn);

    size_t total4 = (size_t)BB * HH * SSEQ * SSEQ / 4;
    unsigned blocks = (unsigned)((total4 + 255) / 256);
    attn_norm<<<blocks, 256>>>(attn);
}